// round 2
// baseline (speedup 1.0000x reference)
#include <cuda_runtime.h>

#define BB 2
#define TT 2048
#define DD 1024
#define HH 16
#define DH 64
#define NEGV (-65504.0f)

// Scratch (allowed: __device__ globals, no runtime allocation)
__device__ float g_Q[BB*TT*DD];
__device__ float g_K[BB*TT*DD];
__device__ float g_V[BB*TT*DD];
__device__ float g_O[BB*TT*DD];

__device__ __forceinline__ float* sel_buf(int s) {
    switch (s) {
        case 0: return g_Q;
        case 1: return g_K;
        case 2: return g_V;
        default: return g_O;
    }
}

// ---------------------------------------------------------------------------
// SGEMM: C[M,N] = A[M,K] @ W[K,N] + bias[N]   (all row-major, fp32)
// 128x128 block tile, BK=16, 8x8 per-thread, 256 threads.
// asel/csel >= 0 select a __device__ scratch buffer instead of the pointer arg.
// ---------------------------------------------------------------------------
__global__ __launch_bounds__(256) void sgemm_bias(
    const float* __restrict__ Ap, const float* __restrict__ W,
    const float* __restrict__ bias, float* __restrict__ Cp,
    int M, int N, int K, int asel, int csel)
{
    constexpr int BM = 128, BN = 128, BK = 16, TM = 8, TN = 8;
    __shared__ float As[BK][BM];
    __shared__ float Ws[BK][BN];

    const float* A = (asel >= 0) ? sel_buf(asel) : Ap;
    float*       C = (csel >= 0) ? sel_buf(csel) : Cp;

    const int tid  = threadIdx.x;
    const int br   = blockIdx.y;   // M tile
    const int bc   = blockIdx.x;   // N tile
    const int trow = tid / (BN / TN);  // 0..15
    const int tcol = tid % (BN / TN);  // 0..15

    float acc[TM][TN];
    #pragma unroll
    for (int i = 0; i < TM; i++)
        #pragma unroll
        for (int j = 0; j < TN; j++) acc[i][j] = 0.f;

    const int aRow  = tid / (BK / 4);  // 0..63
    const int aCol4 = tid % (BK / 4);  // 0..3
    const int wRow  = tid / (BN / 4);  // 0..7
    const int wCol4 = tid % (BN / 4);  // 0..31

    const float* Ab = A + (size_t)br * BM * K;
    const float* Wb = W + bc * BN;

    for (int k0 = 0; k0 < K; k0 += BK) {
        #pragma unroll
        for (int i = 0; i < BM; i += 64) {
            float4 v = *reinterpret_cast<const float4*>(
                Ab + (size_t)(aRow + i) * K + k0 + aCol4 * 4);
            As[aCol4 * 4 + 0][aRow + i] = v.x;
            As[aCol4 * 4 + 1][aRow + i] = v.y;
            As[aCol4 * 4 + 2][aRow + i] = v.z;
            As[aCol4 * 4 + 3][aRow + i] = v.w;
        }
        #pragma unroll
        for (int i = 0; i < BK; i += 8) {
            float4 v = *reinterpret_cast<const float4*>(
                Wb + (size_t)(k0 + wRow + i) * N + wCol4 * 4);
            *reinterpret_cast<float4*>(&Ws[wRow + i][wCol4 * 4]) = v;
        }
        __syncthreads();

        #pragma unroll
        for (int kk = 0; kk < BK; kk++) {
            float ra[TM], rb[TN];
            #pragma unroll
            for (int i = 0; i < TM; i++) ra[i] = As[kk][trow * TM + i];
            #pragma unroll
            for (int j = 0; j < TN; j++) rb[j] = Ws[kk][tcol * TN + j];
            #pragma unroll
            for (int i = 0; i < TM; i++)
                #pragma unroll
                for (int j = 0; j < TN; j++)
                    acc[i][j] += ra[i] * rb[j];
        }
        __syncthreads();
    }

    #pragma unroll
    for (int i = 0; i < TM; i++) {
        const int row = br * BM + trow * TM + i;
        #pragma unroll
        for (int j = 0; j < TN; j += 4) {
            const int col = bc * BN + tcol * TN + j;
            float4 o;
            o.x = acc[i][j + 0] + bias[col + 0];
            o.y = acc[i][j + 1] + bias[col + 1];
            o.z = acc[i][j + 2] + bias[col + 2];
            o.w = acc[i][j + 3] + bias[col + 3];
            *reinterpret_cast<float4*>(C + (size_t)row * N + col) = o;
        }
    }
}

// ---------------------------------------------------------------------------
// Flash-style attention, fp32. One query row per thread (q, o in registers),
// K/V tiles of 64 keys in smem (broadcast reads), online softmax.
// Masked keys are skipped: exp(NEG - m) underflows to exactly 0 in fp32, so
// they contribute 0 to numerator and denominator in the reference as well.
// grid = (B*H, T/128), block = 128
// ---------------------------------------------------------------------------
__global__ __launch_bounds__(128) void attn_kernel(const int* __restrict__ mask)
{
    const int bh = blockIdx.x;
    const int b  = bh / HH;
    const int h  = bh % HH;
    const int r  = blockIdx.y * 128 + threadIdx.x;   // query row in [0, T)
    const int tid = threadIdx.x;

    __shared__ float sK[64][DH];
    __shared__ float sV[64][DH];
    __shared__ int   sM[64];

    // load q row, pre-scaled by 1/32 (exact power of two)
    const float* Qp = g_Q + ((size_t)b * TT + r) * DD + h * DH;
    float q[DH];
    #pragma unroll
    for (int d = 0; d < DH; d += 4) {
        float4 v = *reinterpret_cast<const float4*>(Qp + d);
        q[d + 0] = v.x * 0.03125f;
        q[d + 1] = v.y * 0.03125f;
        q[d + 2] = v.z * 0.03125f;
        q[d + 3] = v.w * 0.03125f;
    }

    float o[DH];
    #pragma unroll
    for (int d = 0; d < DH; d++) o[d] = 0.f;
    float m = -1e30f, l = 0.f;

    for (int kt = 0; kt < TT; kt += 64) {
        // cooperative tile load: 64 keys x 64 dims (float4 granules)
        for (int idx = tid; idx < 64 * 16; idx += 128) {
            const int row = idx / 16;
            const int c4  = idx % 16;
            const size_t g = ((size_t)b * TT + kt + row) * DD + h * DH + c4 * 4;
            *reinterpret_cast<float4*>(&sK[row][c4 * 4]) =
                *reinterpret_cast<const float4*>(g_K + g);
            *reinterpret_cast<float4*>(&sV[row][c4 * 4]) =
                *reinterpret_cast<const float4*>(g_V + g);
        }
        if (tid < 64) sM[tid] = mask[b * TT + kt + tid];
        __syncthreads();

        #pragma unroll 2
        for (int j = 0; j < 64; j++) {
            if (sM[j] != 0) {                 // uniform across warp: no divergence
                float s = 0.f;
                const float4* kr = reinterpret_cast<const float4*>(sK[j]);
                #pragma unroll
                for (int d4 = 0; d4 < 16; d4++) {
                    float4 kv = kr[d4];
                    s += q[d4 * 4 + 0] * kv.x + q[d4 * 4 + 1] * kv.y
                       + q[d4 * 4 + 2] * kv.z + q[d4 * 4 + 3] * kv.w;
                }
                if (s > m) {                  // rare (O(log T) per row)
                    const float c = __expf(m - s);
                    l *= c;
                    #pragma unroll
                    for (int d = 0; d < DH; d++) o[d] *= c;
                    m = s;
                }
                const float p = __expf(s - m);
                l += p;
                const float4* vr = reinterpret_cast<const float4*>(sV[j]);
                #pragma unroll
                for (int d4 = 0; d4 < 16; d4++) {
                    float4 vv = vr[d4];
                    o[d4 * 4 + 0] += p * vv.x;
                    o[d4 * 4 + 1] += p * vv.y;
                    o[d4 * 4 + 2] += p * vv.z;
                    o[d4 * 4 + 3] += p * vv.w;
                }
            }
        }
        __syncthreads();
    }

    const float inv = 1.f / l;
    float* Op = g_O + ((size_t)b * TT + r) * DD + h * DH;
    #pragma unroll
    for (int d = 0; d < DH; d += 4) {
        float4 v;
        v.x = o[d + 0] * inv;
        v.y = o[d + 1] * inv;
        v.z = o[d + 2] * inv;
        v.w = o[d + 3] * inv;
        *reinterpret_cast<float4*>(Op + d) = v;
    }
}

// ---------------------------------------------------------------------------
// Launch: 3 projection GEMMs -> attention -> output GEMM. Default stream,
// kernel launches only (graph-capturable), no allocations.
// ---------------------------------------------------------------------------
extern "C" void kernel_launch(void* const* d_in, const int* in_sizes, int n_in,
                              void* d_out, int out_size)
{
    const float* q    = (const float*)d_in[0];
    const float* k    = (const float*)d_in[1];
    const float* v    = (const float*)d_in[2];
    const int*   mask = (const int*)  d_in[3];
    const float* Wq   = (const float*)d_in[4];
    const float* bq   = (const float*)d_in[5];
    const float* Wk   = (const float*)d_in[6];
    const float* bk   = (const float*)d_in[7];
    const float* Wv   = (const float*)d_in[8];
    const float* bv   = (const float*)d_in[9];
    const float* Wo   = (const float*)d_in[10];
    const float* bo   = (const float*)d_in[11];
    float* out = (float*)d_out;

    const int M = BB * TT;   // 4096
    const int N = DD;        // 1024
    const int K = DD;        // 1024

    dim3 ggrid(N / 128, M / 128);   // (8, 32)

    sgemm_bias<<<ggrid, 256>>>(q, Wq, bq, nullptr, M, N, K, -1, 0);  // -> g_Q
    sgemm_bias<<<ggrid, 256>>>(k, Wk, bk, nullptr, M, N, K, -1, 1);  // -> g_K
    sgemm_bias<<<ggrid, 256>>>(v, Wv, bv, nullptr, M, N, K, -1, 2);  // -> g_V

    attn_kernel<<<dim3(BB * HH, TT / 128), 128>>>(mask);             // -> g_O

    sgemm_bias<<<ggrid, 256>>>(nullptr, Wo, bo, out, M, N, K, 3, -1);
}